// round 2
// baseline (speedup 1.0000x reference)
#include <cuda_runtime.h>
#include <math.h>

#define N_RES 8192
#define N_IN  128
#define BATCH 16
#define LEAK  0.9f
#define CAP   1280          // per-row bucket capacity; Poisson(818), P(>1280) ~ 1e-50

// ---------------------------------------------------------------------------
// Scratch (allocation-free __device__ globals)
__device__ __align__(16) float  g_z[N_RES * BATCH];        // 512 KB bias + input-spmm accumulator
__device__ __align__(16) float  g_state_T[N_RES * BATCH];  // 512 KB, [row][batch], L2/L1-resident
__device__ __align__(16) float  g_x_T[N_IN * BATCH];       // 8 KB
__device__ int    g_cursor[N_RES];                         // per-row fill counters
__device__ __align__(16) float2 g_bucket[(size_t)N_RES * CAP];  // 84 MB: packed (val, col-bits)

__device__ __forceinline__ void red_add_v4(float* p, float a, float b, float c, float d) {
    asm volatile("red.global.add.v4.f32 [%0], {%1,%2,%3,%4};"
                 :: "l"(p), "f"(a), "f"(b), "f"(c), "f"(d) : "memory");
}

// ---------------------------------------------------------------------------
// Kernel 1: init z with biases, zero cursors, transpose state and x.
__global__ void k_init(const float* __restrict__ state,
                       const float* __restrict__ x,
                       const float* __restrict__ res_bias,
                       const float* __restrict__ in_bias) {
    int i = blockIdx.x * blockDim.x + threadIdx.x;
    if (i < N_RES * BATCH) {
        int r = i >> 4;              // i / BATCH
        int b = i & (BATCH - 1);
        g_z[i]       = res_bias[r] + in_bias[r];
        g_state_T[i] = state[b * N_RES + r];
    }
    if (i < N_IN * BATCH) {
        int r = i >> 4;
        int b = i & (BATCH - 1);
        g_x_T[i] = x[b * N_IN + r];
    }
    if (i < N_RES) g_cursor[i] = 0;
}

// ---------------------------------------------------------------------------
// Kernel 2: input SpMM (small: ~105K entries). Atomic scatter is fine here.
__global__ void k_in_spmm(const float* __restrict__ vals,
                          const int*   __restrict__ rows,
                          const int*   __restrict__ cols,
                          int nnz) {
    int i = blockIdx.x * blockDim.x + threadIdx.x;
    if (i >= nnz) return;
    float v = vals[i];
    int r = rows[i];
    int c = cols[i];
    const float4* s = reinterpret_cast<const float4*>(g_x_T + c * BATCH);
    float4 s0 = s[0], s1 = s[1], s2 = s[2], s3 = s[3];
    float* zp = g_z + r * BATCH;
    red_add_v4(zp + 0,  v * s0.x, v * s0.y, v * s0.z, v * s0.w);
    red_add_v4(zp + 4,  v * s1.x, v * s1.y, v * s1.z, v * s1.w);
    red_add_v4(zp + 8,  v * s2.x, v * s2.y, v * s2.z, v * s2.w);
    red_add_v4(zp + 12, v * s3.x, v * s3.y, v * s3.z, v * s3.w);
}

// ---------------------------------------------------------------------------
// Kernel 3: bucket the reservoir COO entries by row (scan-free counting sort).
// Scalar int atomics on 8192 addresses pipeline at ~1/cyc/slice in L2.
__global__ void __launch_bounds__(256) k_scatter(const float* __restrict__ vals,
                                                 const int*   __restrict__ rows,
                                                 const int*   __restrict__ cols,
                                                 int nnz) {
    int i = blockIdx.x * blockDim.x + threadIdx.x;
    if (i >= nnz) return;
    int r = rows[i];
    int pos = atomicAdd(&g_cursor[r], 1);
    if (pos < CAP) {
        g_bucket[(size_t)r * CAP + pos] =
            make_float2(vals[i], __int_as_float(cols[i]));
    }
}

// ---------------------------------------------------------------------------
// Kernel 4: gather per row with register accumulation + fused epilogue.
// One warp per row. Half-warp = one entry; lane%16 = batch index.
// state gather is 64B coalesced per half-warp, no atomics anywhere.
__global__ void __launch_bounds__(256) k_gather(const float* __restrict__ state,
                                                float* __restrict__ out) {
    int warp_id = (blockIdx.x * blockDim.x + threadIdx.x) >> 5;
    if (warp_id >= N_RES) return;
    int r    = warp_id;
    int lane = threadIdx.x & 31;
    int half = lane >> 4;          // 0 or 1: which entry of the pair
    int b    = lane & 15;          // batch index

    int n = g_cursor[r];
    if (n > CAP) n = CAP;
    const float2* __restrict__ seg = g_bucket + (size_t)r * CAP;

    float acc = 0.0f;
    int j = half;
    // 2x unrolled: 4 entries in flight per warp iteration
    for (; j + 2 < n; j += 4) {
        float2 e0 = seg[j];
        float2 e1 = seg[j + 2];
        acc = fmaf(e0.x, g_state_T[__float_as_int(e0.y) * BATCH + b], acc);
        acc = fmaf(e1.x, g_state_T[__float_as_int(e1.y) * BATCH + b], acc);
    }
    for (; j < n; j += 2) {
        float2 e0 = seg[j];
        acc = fmaf(e0.x, g_state_T[__float_as_int(e0.y) * BATCH + b], acc);
    }
    // combine the two half-warp partials (same batch lane in each half)
    acc += __shfl_xor_sync(0xffffffffu, acc, 16);

    if (lane < BATCH) {
        float z = acc + g_z[r * BATCH + lane];       // biases + input spmm
        float s = state[lane * N_RES + r];
        out[lane * N_RES + r] = (1.0f - LEAK) * s + LEAK * erff(z);
    }
}

// ---------------------------------------------------------------------------
extern "C" void kernel_launch(void* const* d_in, const int* in_sizes, int n_in,
                              void* d_out, int out_size) {
    const float* state    = (const float*)d_in[0];
    const float* x        = (const float*)d_in[1];
    const float* res_vals = (const float*)d_in[2];
    const int*   res_rows = (const int*)  d_in[3];
    const int*   res_cols = (const int*)  d_in[4];
    const float* res_bias = (const float*)d_in[5];
    const float* in_vals  = (const float*)d_in[6];
    const int*   in_rows  = (const int*)  d_in[7];
    const int*   in_cols  = (const int*)  d_in[8];
    const float* in_bias  = (const float*)d_in[9];
    float* out = (float*)d_out;

    int res_nnz = in_sizes[2];
    int in_nnz  = in_sizes[6];

    int n_init = N_RES * BATCH;
    k_init<<<(n_init + 255) / 256, 256>>>(state, x, res_bias, in_bias);

    k_in_spmm<<<(in_nnz + 255) / 256, 256>>>(in_vals, in_rows, in_cols, in_nnz);

    k_scatter<<<(res_nnz + 255) / 256, 256>>>(res_vals, res_rows, res_cols, res_nnz);

    int n_gather_threads = N_RES * 32;
    k_gather<<<(n_gather_threads + 255) / 256, 256>>>(state, out);
}

// round 3
// speedup vs baseline: 1.2313x; 1.2313x over previous
#include <cuda_runtime.h>
#include <math.h>

#define N_RES 8192
#define N_IN  128
#define BATCH 16
#define LEAK  0.9f
#define NQ    4            // column quarters (shard dimension)
#define QCAP  320          // per-(row,quarter) capacity; Poisson(205), 320 ~ 8 sigma

// ---------------------------------------------------------------------------
// Scratch (allocation-free __device__ globals)
__device__ __align__(16) float  g_z[N_RES * BATCH];        // bias + input-spmm accumulator
__device__ __align__(16) float  g_state_T[N_RES * BATCH];  // [row][batch]; quarter q = 128KB slice
__device__ __align__(16) float  g_x_T[N_IN * BATCH];
__device__ int    g_cursor[N_RES * NQ];                    // 32768 shard cursors
__device__ __align__(16) float2 g_bucket[(size_t)N_RES * NQ * QCAP];  // 84 MB

__device__ __forceinline__ void red_add_v4(float* p, float a, float b, float c, float d) {
    asm volatile("red.global.add.v4.f32 [%0], {%1,%2,%3,%4};"
                 :: "l"(p), "f"(a), "f"(b), "f"(c), "f"(d) : "memory");
}
__device__ __forceinline__ float2 ldcg_f2(const float2* p) {
    float2 r;
    asm volatile("ld.global.cg.v2.f32 {%0,%1}, [%2];" : "=f"(r.x), "=f"(r.y) : "l"(p));
    return r;
}

// ---------------------------------------------------------------------------
// Kernel 1: init z with biases, zero shard cursors, transpose state and x.
__global__ void k_init(const float* __restrict__ state,
                       const float* __restrict__ x,
                       const float* __restrict__ res_bias,
                       const float* __restrict__ in_bias) {
    int i = blockIdx.x * blockDim.x + threadIdx.x;
    if (i < N_RES * BATCH) {
        int r = i >> 4;
        int b = i & (BATCH - 1);
        g_z[i]       = res_bias[r] + in_bias[r];
        g_state_T[i] = state[b * N_RES + r];
    }
    if (i < N_IN * BATCH) {
        int r = i >> 4;
        int b = i & (BATCH - 1);
        g_x_T[i] = x[b * N_IN + r];
    }
    if (i < N_RES * NQ) g_cursor[i] = 0;
}

// ---------------------------------------------------------------------------
// Kernel 2: input SpMM (small: ~105K entries) via vector reductions.
__global__ void k_in_spmm(const float* __restrict__ vals,
                          const int*   __restrict__ rows,
                          const int*   __restrict__ cols,
                          int nnz) {
    int i = blockIdx.x * blockDim.x + threadIdx.x;
    if (i >= nnz) return;
    float v = vals[i];
    int r = rows[i];
    int c = cols[i];
    const float4* s = reinterpret_cast<const float4*>(g_x_T + c * BATCH);
    float4 s0 = s[0], s1 = s[1], s2 = s[2], s3 = s[3];
    float* zp = g_z + r * BATCH;
    red_add_v4(zp + 0,  v * s0.x, v * s0.y, v * s0.z, v * s0.w);
    red_add_v4(zp + 4,  v * s1.x, v * s1.y, v * s1.z, v * s1.w);
    red_add_v4(zp + 8,  v * s2.x, v * s2.y, v * s2.z, v * s2.w);
    red_add_v4(zp + 12, v * s3.x, v * s3.y, v * s3.z, v * s3.w);
}

// ---------------------------------------------------------------------------
// Kernel 3: bucket reservoir entries by (row, col-quarter).
// 4 entries per thread = 4 independent atomic chains in flight.
__global__ void __launch_bounds__(256) k_scatter(const float* __restrict__ vals,
                                                 const int*   __restrict__ rows,
                                                 const int*   __restrict__ cols,
                                                 int nnz) {
    int i0 = (blockIdx.x * blockDim.x + threadIdx.x) * 4;
#pragma unroll
    for (int k = 0; k < 4; k++) {
        int i = i0 + k;
        if (i < nnz) {
            int   r = rows[i];
            int   c = cols[i];
            float v = vals[i];
            int   q = c >> 11;                 // column quarter
            int shard = r * NQ + q;
            int pos = atomicAdd(&g_cursor[shard], 1);
            if (pos < QCAP) {
                g_bucket[(size_t)shard * QCAP + pos] =
                    make_float2(v, __int_as_float(c));
            }
        }
    }
}

// ---------------------------------------------------------------------------
// Kernel 4: gather. One warp per row; half-warp = one entry; lane&15 = batch.
// Loops the 4 column quarters in order: state slice per quarter = 128KB, fits
// L1 (seg stream bypasses L1 via .cg). Register accumulation, fused epilogue.
__global__ void __launch_bounds__(256) k_gather(const float* __restrict__ state,
                                                float* __restrict__ out) {
    int warp_id = (blockIdx.x * blockDim.x + threadIdx.x) >> 5;
    if (warp_id >= N_RES) return;
    int r    = warp_id;
    int lane = threadIdx.x & 31;
    int half = lane >> 4;
    int b    = lane & 15;

    float acc = 0.0f;
#pragma unroll
    for (int q = 0; q < NQ; q++) {
        int shard = r * NQ + q;
        int n = g_cursor[shard];
        if (n > QCAP) n = QCAP;
        const float2* __restrict__ seg = g_bucket + (size_t)shard * QCAP;

        int j = half;
        // 4 entries in flight per half-warp
        for (; j + 6 < n; j += 8) {
            float2 e0 = ldcg_f2(seg + j);
            float2 e1 = ldcg_f2(seg + j + 2);
            float2 e2 = ldcg_f2(seg + j + 4);
            float2 e3 = ldcg_f2(seg + j + 6);
            float s0 = g_state_T[__float_as_int(e0.y) * BATCH + b];
            float s1 = g_state_T[__float_as_int(e1.y) * BATCH + b];
            float s2 = g_state_T[__float_as_int(e2.y) * BATCH + b];
            float s3 = g_state_T[__float_as_int(e3.y) * BATCH + b];
            acc = fmaf(e0.x, s0, acc);
            acc = fmaf(e1.x, s1, acc);
            acc = fmaf(e2.x, s2, acc);
            acc = fmaf(e3.x, s3, acc);
        }
        for (; j < n; j += 2) {
            float2 e0 = ldcg_f2(seg + j);
            acc = fmaf(e0.x, g_state_T[__float_as_int(e0.y) * BATCH + b], acc);
        }
    }
    // combine the two half-warp partials
    acc += __shfl_xor_sync(0xffffffffu, acc, 16);

    if (lane < BATCH) {
        float z = acc + g_z[r * BATCH + lane];
        float s = state[lane * N_RES + r];
        out[lane * N_RES + r] = (1.0f - LEAK) * s + LEAK * erff(z);
    }
}

// ---------------------------------------------------------------------------
extern "C" void kernel_launch(void* const* d_in, const int* in_sizes, int n_in,
                              void* d_out, int out_size) {
    const float* state    = (const float*)d_in[0];
    const float* x        = (const float*)d_in[1];
    const float* res_vals = (const float*)d_in[2];
    const int*   res_rows = (const int*)  d_in[3];
    const int*   res_cols = (const int*)  d_in[4];
    const float* res_bias = (const float*)d_in[5];
    const float* in_vals  = (const float*)d_in[6];
    const int*   in_rows  = (const int*)  d_in[7];
    const int*   in_cols  = (const int*)  d_in[8];
    const float* in_bias  = (const float*)d_in[9];
    float* out = (float*)d_out;

    int res_nnz = in_sizes[2];
    int in_nnz  = in_sizes[6];

    k_init<<<(N_RES * BATCH + 255) / 256, 256>>>(state, x, res_bias, in_bias);

    k_in_spmm<<<(in_nnz + 255) / 256, 256>>>(in_vals, in_rows, in_cols, in_nnz);

    int scatter_threads = (res_nnz + 3) / 4;
    k_scatter<<<(scatter_threads + 255) / 256, 256>>>(res_vals, res_rows, res_cols, res_nnz);

    k_gather<<<(N_RES * 32 + 255) / 256, 256>>>(state, out);
}